// round 15
// baseline (speedup 1.0000x reference)
#include <cuda_runtime.h>
#include <cuda_bf16.h>

#define BX    32
#define RPW   2              // rows per warp
#define BY    8              // rows per block (4 warps x 2)
#define IND   384
#define OUTD  377
#define BATCH 32
#define NT    128
#define CHUNK_F4 49          // 48 f4 payload (4 px) + 1 f4 pad -> 784B stride
#define NCH   8              // chunks per row (4 px each)

// D[k][n] = 2*cos(pi*k*(2n+1)/14), compile-time constants -> FFMA-imm
__device__ static constexpr float DC[7][7] = {
  { 2.0f, 2.0f, 2.0f, 2.0f, 2.0f, 2.0f, 2.0f },
  { 1.9498558243636472f,  1.5636629649360596f,  0.8677674782351162f, 0.0f,
   -0.8677674782351162f, -1.5636629649360596f, -1.9498558243636472f },
  { 1.8019377358048383f,  0.4450418679126288f, -1.2469796037174672f, -2.0f,
   -1.2469796037174672f,  0.4450418679126288f,  1.8019377358048383f },
  { 1.5636629649360596f, -0.8677674782351162f, -1.9498558243636472f, 0.0f,
    1.9498558243636472f,  0.8677674782351162f, -1.5636629649360596f },
  { 1.2469796037174672f, -1.8019377358048383f, -0.4450418679126288f, 2.0f,
   -0.4450418679126288f, -1.8019377358048383f,  1.2469796037174672f },
  { 0.8677674782351162f, -1.9498558243636472f,  1.5636629649360596f, 0.0f,
   -1.5636629649360596f,  1.9498558243636472f, -0.8677674782351162f },
  { 0.4450418679126288f, -1.2469796037174672f,  1.8019377358048383f, -2.0f,
    1.8019377358048383f, -1.2469796037174672f,  0.4450418679126288f }
};

__device__ __forceinline__ float ldg_keep(const float* p, unsigned long long pol)
{
    float v;
    asm volatile("ld.global.nc.L2::cache_hint.f32 %0, [%1], %2;"
                 : "=f"(v) : "l"(p), "l"(pol));
    return v;
}

__device__ __forceinline__ void vert7(const float* x, float Vk[7])
{
    float sx[3], dx[3];
    #pragma unroll
    for (int m = 0; m < 3; m++) { sx[m] = x[m] + x[6 - m]; dx[m] = x[m] - x[6 - m]; }
    #pragma unroll
    for (int k = 0; k < 7; k++) {
        float s;
        if ((k & 1) == 0) {
            s = DC[k][3] * x[3];
            #pragma unroll
            for (int m = 0; m < 3; m++) s = fmaf(DC[k][m], sx[m], s);
        } else {
            s = DC[k][0] * dx[0];
            s = fmaf(DC[k][1], dx[1], s);
            s = fmaf(DC[k][2], dx[2], s);
        }
        Vk[k] = s;
    }
}

__global__ __launch_bounds__(NT)
void dct_conv_kernel(const float* __restrict__ X, float* __restrict__ out)
{
    __shared__ float  Vs[4][7][40];            // warp-private vertical results
    __shared__ float4 Osh4[4][NCH * CHUNK_F4]; // warp-private staging (1 row)

    const int tid  = threadIdx.x;
    const int w    = tid >> 5;
    const int lane = tid & 31;
    // lane -> pixel map for conflict-free 4px-chunk staging:
    // chunk q = lane&7, pos-in-chunk r4 = lane>>3, pixel = 4q + r4
    const int q    = lane & 7;
    const int r4   = lane >> 3;
    const int px   = (q << 2) + r4;

    const int x0   = blockIdx.x * BX;
    const int y0   = blockIdx.y * BY;
    const int b    = blockIdx.z;

    const int nvx     = min(BX, OUTD - x0);
    const int nchunks = (nvx + 3) >> 2;          // 8 or 7
    const long long ZF = (long long)BATCH * OUTD * OUTD;
    const int gy = y0 + RPW * w;                 // first output row of this warp

    // cache policies: input lingers in L2, output leaves immediately
    unsigned long long pol_keep, pol_stream;
    asm volatile("createpolicy.fractional.L2::evict_last.b64 %0, 1.0;"
                 : "=l"(pol_keep));
    asm volatile("createpolicy.fractional.L2::evict_first.b64 %0, 1.0;"
                 : "=l"(pol_stream));

    // ---- load 8-tall input columns once (covers both output rows) ----
    float c0[8], c1[8];
    {
        const float* Xb = X + (size_t)b * IND * IND;
        const int gx0   = x0 + lane;             // always < IND
        const int gx1   = x0 + 32 + lane;        // halo cols (lanes 0..5)
        const bool ok1  = (lane < 6) && (gx1 < IND);
        #pragma unroll
        for (int m = 0; m < 8; m++) {
            int  gr = gy + m;
            bool rv = gr < IND;
            const float* rowp = Xb + (size_t)gr * IND;
            c0[m] = rv          ? ldg_keep(rowp + gx0, pol_keep) : 0.0f;
            c1[m] = (rv && ok1) ? ldg_keep(rowp + gx1, pol_keep) : 0.0f;
        }
    }

    #pragma unroll
    for (int r = 0; r < RPW; r++) {
        const int  y      = gy + r;
        const bool row_ok = y < OUTD;

        // ---- vertical DCT for this sub-row (windows [r..r+6]) ----
        {
            float V0[7], V1[7];
            vert7(&c0[r], V0);
            vert7(&c1[r], V1);
            #pragma unroll
            for (int k = 0; k < 7; k++) {
                Vs[w][k][lane] = V0[k];
                if (lane < 6) Vs[w][k][32 + lane] = V1[k];
            }
        }
        __syncwarp();

        // ---- horizontal pass: lane -> pixel px; 4px-chunk staging ----
        // f4 addr = q*49 + r4*12 + c -> banks (4q + 16r4 + 4c) % 32:
        // conflict-free per 8-lane phase (phase = fixed r4, q = 0..7).
        {
            float4* dst = &Osh4[w][q * CHUNK_F4 + r4 * 12];
            float b0 = 0.f, b1 = 0.f, b2 = 0.f;
            #pragma unroll
            for (int k = 0; k < 7; k++) {
                float v[7];
                #pragma unroll
                for (int n = 0; n < 7; n++) v[n] = Vs[w][k][px + n];
                float sv[3], dv[3];
                #pragma unroll
                for (int n = 0; n < 3; n++) { sv[n] = v[n] + v[6 - n]; dv[n] = v[n] - v[6 - n]; }

                #pragma unroll
                for (int i = 0; i < 7; i++) {
                    float a;
                    if ((i & 1) == 0) {
                        a = DC[i][3] * v[3];
                        #pragma unroll
                        for (int n = 0; n < 3; n++) a = fmaf(DC[i][n], sv[n], a);
                    } else {
                        a = DC[i][0] * dv[0];
                        a = fmaf(DC[i][1], dv[1], a);
                        a = fmaf(DC[i][2], dv[2], a);
                    }

                    const int ch = k * 7 + i;            // compile-time constant
                    if (ch == 0) {
                        int x = x0 + px;
                        if (x < OUTD && row_ok)
                            __stcs(&out[((size_t)b * OUTD + y) * OUTD + x], a);
                    } else {
                        const int pos = (ch - 1) & 3;    // compile-time constant
                        if      (pos == 0) b0 = a;
                        else if (pos == 1) b1 = a;
                        else if (pos == 2) b2 = a;
                        else dst[(ch - 4) >> 2] = make_float4(b0, b1, b2, a);
                    }
                }
            }
        }
        __syncwarp();

        // ---- per-warp TMA bulk writeout: lane j handles 4px chunk j ----
        if (row_ok && lane < nchunks) {
            int sz = (lane == nchunks - 1) ? (nvx - 4 * lane) * 192 : 768;
            const float* gp = out + ZF +
                (((size_t)b * OUTD + y) * OUTD + x0 + 4 * lane) * 48;
            unsigned long long gaddr =
                (unsigned long long)__cvta_generic_to_global((void*)gp);
            unsigned int saddr = (unsigned int)__cvta_generic_to_shared(
                &Osh4[w][lane * CHUNK_F4]);
            asm volatile("fence.proxy.async.shared::cta;" ::: "memory");
            asm volatile(
                "cp.async.bulk.global.shared::cta.bulk_group.L2::cache_hint "
                "[%0], [%1], %2, %3;"
                :: "l"(gaddr), "r"(saddr), "r"(sz), "l"(pol_stream) : "memory");
            asm volatile("cp.async.bulk.commit_group;" ::: "memory");
        }

        // between sub-rows: release staging as soon as bulk READS finish.
        if (r + 1 < RPW) {
            if (row_ok && lane < nchunks)
                asm volatile("cp.async.bulk.wait_group.read 0;" ::: "memory");
            __syncwarp();
        }
    }

    // ---- tail: each committing thread waits its groups before CTA exit ----
    asm volatile("cp.async.bulk.wait_group 0;" ::: "memory");
}

extern "C" void kernel_launch(void* const* d_in, const int* in_sizes, int n_in,
                              void* d_out, int out_size)
{
    const float* X = (const float*)d_in[0];
    float* out = (float*)d_out;

    dim3 grid((OUTD + BX - 1) / BX,   // 12
              (OUTD + BY - 1) / BY,   // 48
              BATCH);                 // 32
    dct_conv_kernel<<<grid, NT>>>(X, out);
}

// round 16
// speedup vs baseline: 1.2886x; 1.2886x over previous
#include <cuda_runtime.h>
#include <cuda_bf16.h>

#define BX    32
#define RPW   2              // rows per warp
#define BY    8              // rows per block (4 warps x 2)
#define IND   384
#define OUTD  377
#define BATCH 32
#define NT    128
#define CHUNK_F4 49          // 48 f4 payload (4 px) + 1 f4 pad -> 784B stride
#define NCH   8              // chunks per row (4 px each)

// D[k][n] = 2*cos(pi*k*(2n+1)/14), compile-time constants -> FFMA-imm
__device__ static constexpr float DC[7][7] = {
  { 2.0f, 2.0f, 2.0f, 2.0f, 2.0f, 2.0f, 2.0f },
  { 1.9498558243636472f,  1.5636629649360596f,  0.8677674782351162f, 0.0f,
   -0.8677674782351162f, -1.5636629649360596f, -1.9498558243636472f },
  { 1.8019377358048383f,  0.4450418679126288f, -1.2469796037174672f, -2.0f,
   -1.2469796037174672f,  0.4450418679126288f,  1.8019377358048383f },
  { 1.5636629649360596f, -0.8677674782351162f, -1.9498558243636472f, 0.0f,
    1.9498558243636472f,  0.8677674782351162f, -1.5636629649360596f },
  { 1.2469796037174672f, -1.8019377358048383f, -0.4450418679126288f, 2.0f,
   -0.4450418679126288f, -1.8019377358048383f,  1.2469796037174672f },
  { 0.8677674782351162f, -1.9498558243636472f,  1.5636629649360596f, 0.0f,
   -1.5636629649360596f,  1.9498558243636472f, -0.8677674782351162f },
  { 0.4450418679126288f, -1.2469796037174672f,  1.8019377358048383f, -2.0f,
    1.8019377358048383f, -1.2469796037174672f,  0.4450418679126288f }
};

// scalar input load with L2 evict-last policy (policy created once, passed in)
__device__ __forceinline__ float ldg_keep(const float* p, unsigned long long pol)
{
    float v;
    asm volatile("ld.global.nc.L2::cache_hint.f32 %0, [%1], %2;"
                 : "=f"(v) : "l"(p), "l"(pol));
    return v;
}

__device__ __forceinline__ void vert7(const float* x, float Vk[7])
{
    float sx[3], dx[3];
    #pragma unroll
    for (int m = 0; m < 3; m++) { sx[m] = x[m] + x[6 - m]; dx[m] = x[m] - x[6 - m]; }
    #pragma unroll
    for (int k = 0; k < 7; k++) {
        float s;
        if ((k & 1) == 0) {
            s = DC[k][3] * x[3];
            #pragma unroll
            for (int m = 0; m < 3; m++) s = fmaf(DC[k][m], sx[m], s);
        } else {
            s = DC[k][0] * dx[0];
            s = fmaf(DC[k][1], dx[1], s);
            s = fmaf(DC[k][2], dx[2], s);
        }
        Vk[k] = s;
    }
}

__global__ __launch_bounds__(NT)
void dct_conv_kernel(const float* __restrict__ X, float* __restrict__ out)
{
    __shared__ float  Vs[4][7][40];            // warp-private vertical results
    __shared__ float4 Osh4[4][NCH * CHUNK_F4]; // warp-private staging (1 row)

    const int tid  = threadIdx.x;
    const int w    = tid >> 5;
    const int lane = tid & 31;
    // lane -> pixel map for conflict-free 4px-chunk staging:
    // chunk q = lane&7, pos-in-chunk r4 = lane>>3, pixel = 4q + r4
    const int q    = lane & 7;
    const int r4   = lane >> 3;
    const int px   = (q << 2) + r4;

    const int x0   = blockIdx.x * BX;
    const int y0   = blockIdx.y * BY;
    const int b    = blockIdx.z;

    const int nvx     = min(BX, OUTD - x0);
    const int nchunks = (nvx + 3) >> 2;          // 8 or 7
    const long long ZF = (long long)BATCH * OUTD * OUTD;
    const int gy = y0 + RPW * w;                 // first output row of this warp

    // input cache policy: keep the small input resident in L2.
    // NOTE (R15 lesson): do NOT hint the store side — output needs full L2
    // residency for write-burst assembly; evict_first cratered DRAM to 60%.
    unsigned long long pol_keep;
    asm volatile("createpolicy.fractional.L2::evict_last.b64 %0, 1.0;"
                 : "=l"(pol_keep));

    // ---- load 8-tall input columns once (covers both output rows) ----
    float c0[8], c1[8];
    {
        const float* Xb = X + (size_t)b * IND * IND;
        const int gx0   = x0 + lane;             // always < IND
        const int gx1   = x0 + 32 + lane;        // halo cols (lanes 0..5)
        const bool ok1  = (lane < 6) && (gx1 < IND);
        #pragma unroll
        for (int m = 0; m < 8; m++) {
            int  gr = gy + m;
            bool rv = gr < IND;
            const float* rowp = Xb + (size_t)gr * IND;
            c0[m] = rv          ? ldg_keep(rowp + gx0, pol_keep) : 0.0f;
            c1[m] = (rv && ok1) ? ldg_keep(rowp + gx1, pol_keep) : 0.0f;
        }
    }

    #pragma unroll
    for (int r = 0; r < RPW; r++) {
        const int  y      = gy + r;
        const bool row_ok = y < OUTD;

        // ---- vertical DCT for this sub-row (windows [r..r+6]) ----
        {
            float V0[7], V1[7];
            vert7(&c0[r], V0);
            vert7(&c1[r], V1);
            #pragma unroll
            for (int k = 0; k < 7; k++) {
                Vs[w][k][lane] = V0[k];
                if (lane < 6) Vs[w][k][32 + lane] = V1[k];
            }
        }
        __syncwarp();

        // ---- horizontal pass: lane -> pixel px; 4px-chunk staging ----
        // f4 addr = q*49 + r4*12 + c -> banks (4q + 16r4 + 4c) % 32:
        // conflict-free per 8-lane phase (phase = fixed r4, q = 0..7).
        {
            float4* dst = &Osh4[w][q * CHUNK_F4 + r4 * 12];
            float b0 = 0.f, b1 = 0.f, b2 = 0.f;
            #pragma unroll
            for (int k = 0; k < 7; k++) {
                float v[7];
                #pragma unroll
                for (int n = 0; n < 7; n++) v[n] = Vs[w][k][px + n];
                float sv[3], dv[3];
                #pragma unroll
                for (int n = 0; n < 3; n++) { sv[n] = v[n] + v[6 - n]; dv[n] = v[n] - v[6 - n]; }

                #pragma unroll
                for (int i = 0; i < 7; i++) {
                    float a;
                    if ((i & 1) == 0) {
                        a = DC[i][3] * v[3];
                        #pragma unroll
                        for (int n = 0; n < 3; n++) a = fmaf(DC[i][n], sv[n], a);
                    } else {
                        a = DC[i][0] * dv[0];
                        a = fmaf(DC[i][1], dv[1], a);
                        a = fmaf(DC[i][2], dv[2], a);
                    }

                    const int ch = k * 7 + i;            // compile-time constant
                    if (ch == 0) {
                        int x = x0 + px;
                        if (x < OUTD && row_ok)
                            __stcs(&out[((size_t)b * OUTD + y) * OUTD + x], a);
                    } else {
                        const int pos = (ch - 1) & 3;    // compile-time constant
                        if      (pos == 0) b0 = a;
                        else if (pos == 1) b1 = a;
                        else if (pos == 2) b2 = a;
                        else dst[(ch - 4) >> 2] = make_float4(b0, b1, b2, a);
                    }
                }
            }
        }
        __syncwarp();

        // ---- per-warp TMA bulk writeout: lane j handles 4px chunk j ----
        // plain bulk store (no cache hint) — see R15 note above.
        if (row_ok && lane < nchunks) {
            int sz = (lane == nchunks - 1) ? (nvx - 4 * lane) * 192 : 768;
            const float* gp = out + ZF +
                (((size_t)b * OUTD + y) * OUTD + x0 + 4 * lane) * 48;
            unsigned long long gaddr =
                (unsigned long long)__cvta_generic_to_global((void*)gp);
            unsigned int saddr = (unsigned int)__cvta_generic_to_shared(
                &Osh4[w][lane * CHUNK_F4]);
            asm volatile("fence.proxy.async.shared::cta;" ::: "memory");
            asm volatile(
                "cp.async.bulk.global.shared::cta.bulk_group [%0], [%1], %2;"
                :: "l"(gaddr), "r"(saddr), "r"(sz) : "memory");
            asm volatile("cp.async.bulk.commit_group;" ::: "memory");
        }

        // between sub-rows: release staging as soon as bulk READS finish.
        if (r + 1 < RPW) {
            if (row_ok && lane < nchunks)
                asm volatile("cp.async.bulk.wait_group.read 0;" ::: "memory");
            __syncwarp();
        }
    }

    // ---- tail: each committing thread waits its groups before CTA exit ----
    asm volatile("cp.async.bulk.wait_group 0;" ::: "memory");
}

extern "C" void kernel_launch(void* const* d_in, const int* in_sizes, int n_in,
                              void* d_out, int out_size)
{
    const float* X = (const float*)d_in[0];
    float* out = (float*)d_out;

    dim3 grid((OUTD + BX - 1) / BX,   // 12
              (OUTD + BY - 1) / BY,   // 48
              BATCH);                 // 32
    dct_conv_kernel<<<grid, NT>>>(X, out);
}